// round 7
// baseline (speedup 1.0000x reference)
#include <cuda_runtime.h>

#define N_NODES 50000
#define N_EDGES 800000
#define D_IN    64
#define D_CAT   256   // SCALES * D_OUT = 4 * 64

// ---------------- scratch (static __device__: no allocations allowed) ----------
__device__ float    g_A[(size_t)N_NODES * D_IN];    // 12.8 MB aggregated x (pre-GEMM)
__device__ float    g_dinv[N_NODES];                // degree, then deg^{-1/2}
__device__ int      g_cnt[N_NODES];                 // in-degree histogram
__device__ int      g_rowstart[N_NODES];            // CSR offsets (exclusive scan)
__device__ int      g_ptr[N_NODES];                 // fill cursor; post-scatter == row end
__device__ int2     g_edge[N_EDGES];                // sorted-by-dst (srcrow, norm-bits)
__device__ unsigned g_mm[2] = {0x7F800000u, 0u};    // min/max bits; atomics idempotent
                                                    // across replays on same input

// ---------------- 1) prep: init dinv/cnt + min/max of edge weights -------------
__global__ void k_prep(const float* __restrict__ ew) {
    int gtid = blockIdx.x * blockDim.x + threadIdx.x;
    if (gtid < N_NODES) { g_dinv[gtid] = 1.0f; g_cnt[gtid] = 0; }  // self-loop w=1

    unsigned lmin = 0x7F800000u, lmax = 0u;
    for (int i = gtid; i < N_EDGES; i += gridDim.x * blockDim.x) {
        unsigned b = __float_as_uint(ew[i]);   // nonneg: uint order == float order
        lmin = min(lmin, b);
        lmax = max(lmax, b);
    }
    lmin = __reduce_min_sync(0xffffffffu, lmin);
    lmax = __reduce_max_sync(0xffffffffu, lmax);
    __shared__ unsigned smin[8], smax[8];
    int wid = threadIdx.x >> 5, lane = threadIdx.x & 31;
    if (lane == 0) { smin[wid] = lmin; smax[wid] = lmax; }
    __syncthreads();
    if (threadIdx.x == 0) {
        unsigned bmin = smin[0], bmax = smax[0];
        for (int w = 1; w < 8; w++) { bmin = min(bmin, smin[w]); bmax = max(bmax, smax[w]); }
        atomicMin(&g_mm[0], bmin);
        atomicMax(&g_mm[1], bmax);
    }
}

// ---------------- 2) weighted degree + in-degree histogram ---------------------
__global__ void k_degcnt(const int* __restrict__ ei, const float* __restrict__ ew) {
    float mn  = __uint_as_float(g_mm[0]);
    float inv = 1.0f / (__uint_as_float(g_mm[1]) - mn);
    int e = blockIdx.x * blockDim.x + threadIdx.x;
    if (e < N_EDGES) {
        int c = ei[N_EDGES + e];               // dst = edge_index[1][e]
        float w = (ew[e] - mn) * inv;
        atomicAdd(&g_dinv[c], w);
        atomicAdd(&g_cnt[c], 1);
    }
}

// ---------------- 3) block 0: exclusive scan of cnt; other blocks: rsqrt -------
__global__ void __launch_bounds__(1024) k_mid() {
    if (blockIdx.x == 0) {
        __shared__ int swarp[32];        // per-warp sums
        __shared__ int s_carry;
        int tid  = threadIdx.x;
        int lane = tid & 31;
        int wid  = tid >> 5;
        if (tid == 0) s_carry = 0;
        __syncthreads();
        for (int base = 0; base < N_NODES; base += 1024) {
            int i = base + tid;
            int v = (i < N_NODES) ? g_cnt[i] : 0;
            // warp-level inclusive scan (shfl)
            int s = v;
#pragma unroll
            for (int off = 1; off < 32; off <<= 1) {
                int t = __shfl_up_sync(0xffffffffu, s, off);
                if (lane >= off) s += t;
            }
            if (lane == 31) swarp[wid] = s;
            __syncthreads();
            if (wid == 0) {                 // scan the 32 warp sums
                int ws = swarp[lane];
                int t2 = ws;
#pragma unroll
                for (int off = 1; off < 32; off <<= 1) {
                    int t = __shfl_up_sync(0xffffffffu, t2, off);
                    if (lane >= off) t2 += t;
                }
                swarp[lane] = t2 - ws;      // exclusive prefix of warp sums
            }
            __syncthreads();
            int excl = s - v + swarp[wid] + s_carry;
            if (i < N_NODES) { g_rowstart[i] = excl; g_ptr[i] = excl; }
            __syncthreads();                // everyone done reading s_carry/swarp
            if (tid == 1023) s_carry += s + swarp[31] - (s - v + swarp[31]) + (s - v);
            // ^ simplify: carry += total = swarp-prefix-of-last + s; but compute directly:
            if (tid == 1023) s_carry = excl + v;   // last exclusive + last value = total
            __syncthreads();
        }
    } else {
        int i = (blockIdx.x - 1) * blockDim.x + threadIdx.x;
        if (i < N_NODES) g_dinv[i] = rsqrtf(g_dinv[i]);   // deg >= 1 (self-loop)
    }
}

// ---------------- 4) scatter edges into CSR slots (counting sort) --------------
__global__ void k_scatter(const int* __restrict__ ei, const float* __restrict__ ew) {
    float mn  = __uint_as_float(g_mm[0]);
    float inv = 1.0f / (__uint_as_float(g_mm[1]) - mn);
    int e = blockIdx.x * blockDim.x + threadIdx.x;
    if (e >= N_EDGES) return;
    int r = ei[e];
    int c = ei[N_EDGES + e];
    float w   = (ew[e] - mn) * inv;
    float nrm = g_dinv[r] * w * g_dinv[c];
    int pos = atomicAdd(&g_ptr[c], 1);
    g_edge[pos] = make_int2(r, __float_as_int(nrm));      // one 8B store
}

// ---------------- 5) owned aggregation: warp per dst node, zero value atomics --
__global__ void __launch_bounds__(256) k_agg(const float* __restrict__ x) {
    int gtid = blockIdx.x * blockDim.x + threadIdx.x;
    int node = gtid >> 5;            // 50000 warps exactly (6250 blocks x 8 warps)
    int lane = gtid & 31;
    if (node >= N_NODES) return;

    int beg = g_rowstart[node];
    int end = g_ptr[node];           // post-scatter cursor == row end
    float di = g_dinv[node];
    float dd = di * di;

    // accumulator init = self-loop term dinv^2 * x[node]
    float2 acc = *(const float2*)(x + (size_t)node * D_IN + lane * 2);
    acc.x *= dd; acc.y *= dd;

    for (int base = beg; base < end; base += 32) {
        int idx = base + lane;
        int2 rec = (idx < end) ? g_edge[idx] : make_int2(0, 0);  // coalesced 8B
        int m = min(32, end - base);
#pragma unroll 8
        for (int i = 0; i < m; i++) {
            int   rr = __shfl_sync(0xffffffffu, rec.x, i);
            float nn = __int_as_float(__shfl_sync(0xffffffffu, rec.y, i));
            float2 xv = *(const float2*)(x + (size_t)rr * D_IN + lane * 2);
            acc.x += xv.x * nn;
            acc.y += xv.y * nn;
        }
    }
    *(float2*)(g_A + (size_t)node * D_IN + lane * 2) = acc;      // single owned store
}

// ---------------- 6) GEMM out = A @ W_cat + b ----------------------------------
// Tile: 64 rows x 256 cols per block, K=64 in chunks of 16; 8x8 acc per thread.
__global__ void __launch_bounds__(256) k_gemm(const float* __restrict__ Ws,
                                              const float* __restrict__ bs,
                                              float* __restrict__ out) {
    __shared__ float xs[64 * 16];    // 4 KB
    __shared__ float ws[16 * 256];   // 16 KB
    const int tx = threadIdx.x & 31;
    const int ty = threadIdx.x >> 5;
    const int row0 = blockIdx.x * 64;

    float acc[8][8];
#pragma unroll
    for (int i = 0; i < 8; i++)
#pragma unroll
        for (int j = 0; j < 8; j++) acc[i][j] = 0.0f;

    for (int kt = 0; kt < 4; kt++) {
#pragma unroll
        for (int s = 0; s < 4; s++) {
            int idx = threadIdx.x + 256 * s;
            int r = idx >> 4, kk = idx & 15;
            int gr = row0 + r;
            xs[idx] = (gr < N_NODES) ? g_A[(size_t)gr * D_IN + kt * 16 + kk] : 0.0f;
        }
        // W_cat col c=(scale*64+j) lives at Ws[((c>>6)*64 + k)*64 + (c&63)]
#pragma unroll
        for (int s = 0; s < 16; s++) {
            int idx = threadIdx.x + 256 * s;
            int kk = idx >> 8, c = idx & 255;
            int k = kt * 16 + kk;
            ws[idx] = Ws[(size_t)((c >> 6) * 64 + k) * 64 + (c & 63)];
        }
        __syncthreads();
#pragma unroll
        for (int k = 0; k < 16; k++) {
            float xa[8];
#pragma unroll
            for (int i = 0; i < 8; i++) xa[i] = xs[(ty * 8 + i) * 16 + k];
            float4 w0 = *(const float4*)&ws[k * 256 + tx * 8];
            float4 w1 = *(const float4*)&ws[k * 256 + tx * 8 + 4];
            float wb[8] = {w0.x, w0.y, w0.z, w0.w, w1.x, w1.y, w1.z, w1.w};
#pragma unroll
            for (int i = 0; i < 8; i++)
#pragma unroll
                for (int j = 0; j < 8; j++) acc[i][j] += xa[i] * wb[j];
        }
        __syncthreads();
    }

#pragma unroll
    for (int i = 0; i < 8; i++) {
        int r = row0 + ty * 8 + i;
        if (r >= N_NODES) break;
#pragma unroll
        for (int j = 0; j < 8; j += 4) {
            int c = tx * 8 + j;
            float4 b = *(const float4*)&bs[c];
            float4 o = make_float4(acc[i][j] + b.x, acc[i][j + 1] + b.y,
                                   acc[i][j + 2] + b.z, acc[i][j + 3] + b.w);
            *(float4*)&out[(size_t)r * D_CAT + c] = o;
        }
    }
}

// ---------------- launch -------------------------------------------------------
extern "C" void kernel_launch(void* const* d_in, const int* in_sizes, int n_in,
                              void* d_out, int out_size) {
    // Resolve inputs by element count (all five distinct):
    //   x=3,200,000 f32 | edge_index=1,600,000 i32 | edge_weight=800,000 f32
    //   Ws=16,384 f32   | bs=256 f32
    const float* x  = nullptr;
    const int*   ei = nullptr;
    const float* ew = nullptr;
    const float* Ws = nullptr;
    const float* bs = nullptr;
    for (int i = 0; i < n_in; i++) {
        switch (in_sizes[i]) {
            case 3200000: x  = (const float*)d_in[i]; break;
            case 1600000: ei = (const int*)d_in[i];   break;
            case  800000: ew = (const float*)d_in[i]; break;
            case   16384: Ws = (const float*)d_in[i]; break;
            case     256: bs = (const float*)d_in[i]; break;
        }
    }
    float* out = (float*)d_out;  // [50000, 256]

    k_prep<<<256, 256>>>(ew);                              // init + minmax
    k_degcnt<<<(N_EDGES + 255) / 256, 256>>>(ei, ew);      // degree + histogram
    k_mid<<<1 + (N_NODES + 1023) / 1024, 1024>>>();        // scan || rsqrt
    k_scatter<<<(N_EDGES + 255) / 256, 256>>>(ei, ew);     // counting sort
    k_agg<<<(N_NODES * 32) / 256, 256>>>(x);               // owned aggregation
    k_gemm<<<(N_NODES + 63) / 64, 256>>>(Ws, bs, out);     // GEMM + bias
}

// round 8
// speedup vs baseline: 1.2732x; 1.2732x over previous
#include <cuda_runtime.h>

#define N_NODES 50000
#define N_EDGES 800000
#define D_IN    64
#define D_CAT   256   // SCALES * D_OUT = 4 * 64

// ---------------- scratch (static __device__: no allocations allowed) ----------
__device__ float4   g_A4[(size_t)N_NODES * (D_IN / 4)];  // 12.8 MB aggregated x, 16B aligned
__device__ float    g_deg[N_NODES];                      // weighted degree (raw)
__device__ float    g_dinv[N_NODES];                     // deg^{-1/2}
__device__ unsigned g_mm[2] = {0x7F800000u, 0u};         // min/max bits (idempotent atomics)

// ---------------- 1) prep: init degree + min/max of edge weights ---------------
__global__ void k_prep(const float* __restrict__ ew) {
    int gtid = blockIdx.x * blockDim.x + threadIdx.x;
    if (gtid < N_NODES) g_deg[gtid] = 1.0f;   // self-loop weight 1 pre-added

    unsigned lmin = 0x7F800000u, lmax = 0u;
    for (int i = gtid; i < N_EDGES; i += gridDim.x * blockDim.x) {
        unsigned b = __float_as_uint(ew[i]);  // nonneg: uint order == float order
        lmin = min(lmin, b);
        lmax = max(lmax, b);
    }
    lmin = __reduce_min_sync(0xffffffffu, lmin);
    lmax = __reduce_max_sync(0xffffffffu, lmax);
    __shared__ unsigned smin[8], smax[8];
    int wid = threadIdx.x >> 5, lane = threadIdx.x & 31;
    if (lane == 0) { smin[wid] = lmin; smax[wid] = lmax; }
    __syncthreads();
    if (threadIdx.x == 0) {
        unsigned bmin = smin[0], bmax = smax[0];
        for (int w = 1; w < 8; w++) { bmin = min(bmin, smin[w]); bmax = max(bmax, smax[w]); }
        atomicMin(&g_mm[0], bmin);
        atomicMax(&g_mm[1], bmax);
    }
}

// ---------------- 2) weighted degree -------------------------------------------
__global__ void k_degree(const int* __restrict__ ei, const float* __restrict__ ew) {
    float mn  = __uint_as_float(g_mm[0]);
    float inv = 1.0f / (__uint_as_float(g_mm[1]) - mn);
    int e = blockIdx.x * blockDim.x + threadIdx.x;
    if (e < N_EDGES) {
        float w = (ew[e] - mn) * inv;
        atomicAdd(&g_deg[ei[N_EDGES + e]], w);   // dst = edge_index[1][e]
    }
}

// ---------------- 3) dinv = rsqrt(deg); A = dinv^2 * x (fused, one pass) -------
__global__ void k_rsqrtself(const float* __restrict__ x) {
    int idx = blockIdx.x * blockDim.x + threadIdx.x;   // over 800000 float4s
    if (idx >= N_NODES * (D_IN / 4)) return;
    int row = idx >> 4;                                // 16 float4 per row
    float di = rsqrtf(g_deg[row]);                     // deg >= 1 (self-loop)
    float dd = di * di;
    float4 v = ((const float4*)x)[idx];
    v.x *= dd; v.y *= dd; v.z *= dd; v.w *= dd;
    g_A4[idx] = v;
    if ((idx & 15) == 0) g_dinv[row] = di;             // one writer per row, no race
}

// ---------------- 4) edge scatter: A[col] += norm * x[row], v4 reductions ------
// Warp owns 32 edges (coalesced meta loads). Inner loop handles 2 edges per
// iteration: half-warp (16 lanes) per edge, float4 gather + red.global.add.v4.
__device__ __forceinline__ void red_add_v4(float* p, float4 v) {
    asm volatile("red.global.add.v4.f32 [%0], {%1,%2,%3,%4};"
                 :: "l"(p), "f"(v.x), "f"(v.y), "f"(v.z), "f"(v.w)
                 : "memory");
}

__global__ void __launch_bounds__(256) k_edges(const int* __restrict__ ei,
                                               const float* __restrict__ ew,
                                               const float* __restrict__ x) {
    int lane  = threadIdx.x & 31;
    int gwarp = (blockIdx.x * blockDim.x + threadIdx.x) >> 5;
    int e = gwarp * 32 + lane;           // N_EDGES = 25000*32: no tail

    float mn  = __uint_as_float(g_mm[0]);
    float inv = 1.0f / (__uint_as_float(g_mm[1]) - mn);

    int   r = ei[e];                     // src = edge_index[0][e]
    int   c = ei[N_EDGES + e];           // dst = edge_index[1][e]
    float w = (ew[e] - mn) * inv;
    float nrm = g_dinv[r] * w * g_dinv[c];

    int half = lane >> 4;                // 0: even edge, 1: odd edge
    int q    = lane & 15;                // float4 index within the 64-float row

#pragma unroll 4
    for (int i = 0; i < 32; i += 2) {
        int   rr = __shfl_sync(0xffffffffu, r,   i + half);
        int   cc = __shfl_sync(0xffffffffu, c,   i + half);
        float nn = __shfl_sync(0xffffffffu, nrm, i + half);
        float4 v = ((const float4*)x)[(size_t)rr * 16 + q];
        v.x *= nn; v.y *= nn; v.z *= nn; v.w *= nn;
        red_add_v4((float*)(g_A4 + (size_t)cc * 16 + q), v);
    }
}

// ---------------- 5) GEMM out = A @ W_cat + b ----------------------------------
// Tile: 64 rows x 256 cols per block, K=64 in chunks of 16; 8x8 acc per thread.
__global__ void __launch_bounds__(256) k_gemm(const float* __restrict__ Ws,
                                              const float* __restrict__ bs,
                                              float* __restrict__ out) {
    __shared__ float xs[64 * 16];    // 4 KB
    __shared__ float ws[16 * 256];   // 16 KB
    const int tx = threadIdx.x & 31;
    const int ty = threadIdx.x >> 5;
    const int row0 = blockIdx.x * 64;
    const float* A = (const float*)g_A4;

    float acc[8][8];
#pragma unroll
    for (int i = 0; i < 8; i++)
#pragma unroll
        for (int j = 0; j < 8; j++) acc[i][j] = 0.0f;

    for (int kt = 0; kt < 4; kt++) {
#pragma unroll
        for (int s = 0; s < 4; s++) {
            int idx = threadIdx.x + 256 * s;
            int r = idx >> 4, kk = idx & 15;
            int gr = row0 + r;
            xs[idx] = (gr < N_NODES) ? A[(size_t)gr * D_IN + kt * 16 + kk] : 0.0f;
        }
        // W_cat col c=(scale*64+j) lives at Ws[((c>>6)*64 + k)*64 + (c&63)]
#pragma unroll
        for (int s = 0; s < 16; s++) {
            int idx = threadIdx.x + 256 * s;
            int kk = idx >> 8, cix = idx & 255;
            int k = kt * 16 + kk;
            ws[idx] = Ws[(size_t)((cix >> 6) * 64 + k) * 64 + (cix & 63)];
        }
        __syncthreads();
#pragma unroll
        for (int k = 0; k < 16; k++) {
            float xa[8];
#pragma unroll
            for (int i = 0; i < 8; i++) xa[i] = xs[(ty * 8 + i) * 16 + k];
            float4 w0 = *(const float4*)&ws[k * 256 + tx * 8];
            float4 w1 = *(const float4*)&ws[k * 256 + tx * 8 + 4];
            float wb[8] = {w0.x, w0.y, w0.z, w0.w, w1.x, w1.y, w1.z, w1.w};
#pragma unroll
            for (int i = 0; i < 8; i++)
#pragma unroll
                for (int j = 0; j < 8; j++) acc[i][j] += xa[i] * wb[j];
        }
        __syncthreads();
    }

#pragma unroll
    for (int i = 0; i < 8; i++) {
        int r = row0 + ty * 8 + i;
        if (r >= N_NODES) break;
#pragma unroll
        for (int j = 0; j < 8; j += 4) {
            int cix = tx * 8 + j;
            float4 b = *(const float4*)&bs[cix];
            float4 o = make_float4(acc[i][j] + b.x, acc[i][j + 1] + b.y,
                                   acc[i][j + 2] + b.z, acc[i][j + 3] + b.w);
            *(float4*)&out[(size_t)r * D_CAT + cix] = o;
        }
    }
}

// ---------------- launch -------------------------------------------------------
extern "C" void kernel_launch(void* const* d_in, const int* in_sizes, int n_in,
                              void* d_out, int out_size) {
    // Resolve inputs by element count (all five distinct):
    //   x=3,200,000 f32 | edge_index=1,600,000 i32 | edge_weight=800,000 f32
    //   Ws=16,384 f32   | bs=256 f32
    const float* x  = nullptr;
    const int*   ei = nullptr;
    const float* ew = nullptr;
    const float* Ws = nullptr;
    const float* bs = nullptr;
    for (int i = 0; i < n_in; i++) {
        switch (in_sizes[i]) {
            case 3200000: x  = (const float*)d_in[i]; break;
            case 1600000: ei = (const int*)d_in[i];   break;
            case  800000: ew = (const float*)d_in[i]; break;
            case   16384: Ws = (const float*)d_in[i]; break;
            case     256: bs = (const float*)d_in[i]; break;
        }
    }
    float* out = (float*)d_out;  // [50000, 256]

    k_prep<<<256, 256>>>(ew);                                   // init deg + minmax
    k_degree<<<(N_EDGES + 255) / 256, 256>>>(ei, ew);           // weighted degree
    k_rsqrtself<<<(N_NODES * 16 + 255) / 256, 256>>>(x);        // dinv + A=dinv^2*x
    k_edges<<<(N_EDGES / 32) / 8, 256>>>(ei, ew, x);            // 3125 blocks, v4 REDs
    k_gemm<<<(N_NODES + 63) / 64, 256>>>(Ws, bs, out);          // GEMM + bias
}

// round 9
// speedup vs baseline: 1.3713x; 1.0771x over previous
#include <cuda_runtime.h>

#define N_NODES 50000
#define N_EDGES 800000
#define D_IN    64
#define D_CAT   256   // SCALES * D_OUT = 4 * 64

// ---------------- scratch (static __device__: no allocations allowed) ----------
__device__ float4             g_A4[(size_t)N_NODES * (D_IN / 4)]; // 12.8 MB aggregated x
__device__ float              g_dinv[N_NODES];                    // deg^{-1/2}
__device__ unsigned long long g_pack[N_NODES];                    // cnt<<52 | sum.32frac
                                                                  // zero at load; re-zeroed
                                                                  // by k_rsqrtself each run
__device__ unsigned           g_mm[2] = {0x7F800000u, 0u};        // min/max bits (idempotent)

// ---- 1) fused: min/max of weights + raw degree (sum,count packed u64 atomic) ---
__global__ void k_prepdeg(const int* __restrict__ ei, const float* __restrict__ ew) {
    unsigned lmin = 0x7F800000u, lmax = 0u;
    for (int e = blockIdx.x * blockDim.x + threadIdx.x; e < N_EDGES;
         e += gridDim.x * blockDim.x) {
        float w = ew[e];
        int   c = ei[N_EDGES + e];                     // dst = edge_index[1][e]
        unsigned b = __float_as_uint(w);               // nonneg: uint order == float order
        lmin = min(lmin, b);
        lmax = max(lmax, b);
        // pack: count in bits[52,64), raw-weight sum as 32-bit fixed point below
        unsigned long long pk = (1ULL << 52) |
                                (unsigned long long)(w * 4294967296.0f);
        atomicAdd(&g_pack[c], pk);
    }
    lmin = __reduce_min_sync(0xffffffffu, lmin);
    lmax = __reduce_max_sync(0xffffffffu, lmax);
    __shared__ unsigned smin[8], smax[8];
    int wid = threadIdx.x >> 5, lane = threadIdx.x & 31;
    if (lane == 0) { smin[wid] = lmin; smax[wid] = lmax; }
    __syncthreads();
    if (threadIdx.x == 0) {
        unsigned bmin = smin[0], bmax = smax[0];
        for (int w = 1; w < 8; w++) { bmin = min(bmin, smin[w]); bmax = max(bmax, smax[w]); }
        atomicMin(&g_mm[0], bmin);
        atomicMax(&g_mm[1], bmax);
    }
}

// ---- 2) dinv = rsqrt(deg), A = dinv^2 * x (one pass); resets g_pack ------------
__global__ void k_rsqrtself(const float* __restrict__ x) {
    int idx = blockIdx.x * blockDim.x + threadIdx.x;   // over 800000 float4s
    if (idx >= N_NODES * (D_IN / 4)) return;
    int row = idx >> 4;                                // 16 float4 per row

    unsigned long long v = g_pack[row];                // warp-broadcast (same row/16 lanes)
    float cnt = (float)(unsigned)(v >> 52);
    float sum = (float)(v & ((1ULL << 52) - 1)) * (1.0f / 4294967296.0f);
    float mn  = __uint_as_float(g_mm[0]);
    float inv = 1.0f / (__uint_as_float(g_mm[1]) - mn);
    float deg = 1.0f + (sum - cnt * mn) * inv;         // 1 = self-loop
    float di  = rsqrtf(deg);
    float dd  = di * di;

    float4 xv = ((const float4*)x)[idx];
    xv.x *= dd; xv.y *= dd; xv.z *= dd; xv.w *= dd;
    g_A4[idx] = xv;
    if ((idx & 15) == 0) {                             // one writer per row (loads of all
        g_dinv[row] = di;                              //  16 lanes precede this store)
        g_pack[row] = 0ull;                            // clean state for next replay
    }
}

// ---- 3) edge scatter: A[col] += norm * x[row], red.global.add.v4.f32 -----------
__device__ __forceinline__ void red_add_v4(float* p, float4 v) {
    asm volatile("red.global.add.v4.f32 [%0], {%1,%2,%3,%4};"
                 :: "l"(p), "f"(v.x), "f"(v.y), "f"(v.z), "f"(v.w)
                 : "memory");
}

__global__ void __launch_bounds__(256) k_edges(const int* __restrict__ ei,
                                               const float* __restrict__ ew,
                                               const float* __restrict__ x) {
    int lane  = threadIdx.x & 31;
    int gwarp = (blockIdx.x * blockDim.x + threadIdx.x) >> 5;
    int e = gwarp * 32 + lane;           // N_EDGES = 25000*32: no tail

    float mn  = __uint_as_float(g_mm[0]);
    float inv = 1.0f / (__uint_as_float(g_mm[1]) - mn);

    int   r = ei[e];                     // src = edge_index[0][e]
    int   c = ei[N_EDGES + e];           // dst = edge_index[1][e]
    float w = (ew[e] - mn) * inv;
    float nrm = g_dinv[r] * w * g_dinv[c];

    int half = lane >> 4;                // 0: even edge, 1: odd edge
    int q    = lane & 15;                // float4 index within the 64-float row

#pragma unroll 4
    for (int i = 0; i < 32; i += 2) {
        int   rr = __shfl_sync(0xffffffffu, r,   i + half);
        int   cc = __shfl_sync(0xffffffffu, c,   i + half);
        float nn = __shfl_sync(0xffffffffu, nrm, i + half);
        float4 v = ((const float4*)x)[(size_t)rr * 16 + q];
        v.x *= nn; v.y *= nn; v.z *= nn; v.w *= nn;
        red_add_v4((float*)(g_A4 + (size_t)cc * 16 + q), v);
    }
}

// ---- 4) GEMM out = A @ W_cat + b  (register double-buffered tiles) -------------
// Tile: 64 rows x 256 cols per block, K=64 in 4 chunks of 16; 8x8 acc per thread.
__global__ void __launch_bounds__(256) k_gemm(const float* __restrict__ Ws,
                                              const float* __restrict__ bs,
                                              float* __restrict__ out) {
    __shared__ float xs[64 * 16];    // 4 KB
    __shared__ float ws[16 * 256];   // 16 KB
    const int tx = threadIdx.x & 31;
    const int ty = threadIdx.x >> 5;
    const int row0 = blockIdx.x * 64;
    const float* A = (const float*)g_A4;

    float acc[8][8];
#pragma unroll
    for (int i = 0; i < 8; i++)
#pragma unroll
        for (int j = 0; j < 8; j++) acc[i][j] = 0.0f;

    float a_reg[4];    // staging: 4 elems of the A tile per thread
    float w_reg[16];   // staging: 16 elems of the W tile per thread

    // preload tile kt=0
#pragma unroll
    for (int s = 0; s < 4; s++) {
        int idx = threadIdx.x + 256 * s;
        int r = idx >> 4, kk = idx & 15;
        int gr = row0 + r;
        a_reg[s] = (gr < N_NODES) ? A[(size_t)gr * D_IN + kk] : 0.0f;
    }
#pragma unroll
    for (int s = 0; s < 16; s++) {
        int idx = threadIdx.x + 256 * s;
        int kk = idx >> 8, cix = idx & 255;
        w_reg[s] = Ws[(size_t)((cix >> 6) * 64 + kk) * 64 + (cix & 63)];
    }

    for (int kt = 0; kt < 4; kt++) {
        // commit staged tile to smem
#pragma unroll
        for (int s = 0; s < 4; s++)  xs[threadIdx.x + 256 * s] = a_reg[s];
#pragma unroll
        for (int s = 0; s < 16; s++) ws[threadIdx.x + 256 * s] = w_reg[s];
        __syncthreads();

        // prefetch tile kt+1 (overlaps with FMA loop below)
        if (kt < 3) {
            int ktn = kt + 1;
#pragma unroll
            for (int s = 0; s < 4; s++) {
                int idx = threadIdx.x + 256 * s;
                int r = idx >> 4, kk = idx & 15;
                int gr = row0 + r;
                a_reg[s] = (gr < N_NODES) ? A[(size_t)gr * D_IN + ktn * 16 + kk] : 0.0f;
            }
#pragma unroll
            for (int s = 0; s < 16; s++) {
                int idx = threadIdx.x + 256 * s;
                int kk = idx >> 8, cix = idx & 255;
                int k = ktn * 16 + kk;
                w_reg[s] = Ws[(size_t)((cix >> 6) * 64 + k) * 64 + (cix & 63)];
            }
        }

#pragma unroll
        for (int k = 0; k < 16; k++) {
            float xa[8];
#pragma unroll
            for (int i = 0; i < 8; i++) xa[i] = xs[(ty * 8 + i) * 16 + k];
            float4 w0 = *(const float4*)&ws[k * 256 + tx * 8];
            float4 w1 = *(const float4*)&ws[k * 256 + tx * 8 + 4];
            float wb[8] = {w0.x, w0.y, w0.z, w0.w, w1.x, w1.y, w1.z, w1.w};
#pragma unroll
            for (int i = 0; i < 8; i++)
#pragma unroll
                for (int j = 0; j < 8; j++) acc[i][j] += xa[i] * wb[j];
        }
        __syncthreads();
    }

#pragma unroll
    for (int i = 0; i < 8; i++) {
        int r = row0 + ty * 8 + i;
        if (r >= N_NODES) break;
#pragma unroll
        for (int j = 0; j < 8; j += 4) {
            int cix = tx * 8 + j;
            float4 b = *(const float4*)&bs[cix];
            float4 o = make_float4(acc[i][j] + b.x, acc[i][j + 1] + b.y,
                                   acc[i][j + 2] + b.z, acc[i][j + 3] + b.w);
            *(float4*)&out[(size_t)r * D_CAT + cix] = o;
        }
    }
}

// ---------------- launch -------------------------------------------------------
extern "C" void kernel_launch(void* const* d_in, const int* in_sizes, int n_in,
                              void* d_out, int out_size) {
    // Resolve inputs by element count (all five distinct):
    //   x=3,200,000 f32 | edge_index=1,600,000 i32 | edge_weight=800,000 f32
    //   Ws=16,384 f32   | bs=256 f32
    const float* x  = nullptr;
    const int*   ei = nullptr;
    const float* ew = nullptr;
    const float* Ws = nullptr;
    const float* bs = nullptr;
    for (int i = 0; i < n_in; i++) {
        switch (in_sizes[i]) {
            case 3200000: x  = (const float*)d_in[i]; break;
            case 1600000: ei = (const int*)d_in[i];   break;
            case  800000: ew = (const float*)d_in[i]; break;
            case   16384: Ws = (const float*)d_in[i]; break;
            case     256: bs = (const float*)d_in[i]; break;
        }
    }
    float* out = (float*)d_out;  // [50000, 256]

    k_prepdeg<<<256, 256>>>(ei, ew);                            // minmax + packed degree
    k_rsqrtself<<<(N_NODES * 16 + 255) / 256, 256>>>(x);        // dinv + A=dinv^2*x + reset
    k_edges<<<(N_EDGES / 32) / 8, 256>>>(ei, ew, x);            // 3125 blocks, v4 REDs
    k_gemm<<<(N_NODES + 63) / 64, 256>>>(Ws, bs, out);          // GEMM + bias (pipelined)
}

// round 10
// speedup vs baseline: 1.3849x; 1.0099x over previous
#include <cuda_runtime.h>
#include <mma.h>

using namespace nvcuda;

#define N_NODES 50000
#define N_EDGES 800000
#define D_IN    64
#define D_CAT   256   // SCALES * D_OUT = 4 * 64

// ---------------- scratch (static __device__: no allocations allowed) ----------
__device__ float4             g_A4[(size_t)N_NODES * (D_IN / 4)]; // 12.8 MB aggregated x
__device__ float              g_dinv[N_NODES];                    // deg^{-1/2}
__device__ unsigned long long g_pack[N_NODES];                    // cnt<<52 | sum.32frac
                                                                  // zero at load; re-zeroed
                                                                  // by k_rsqrtself each run
__device__ unsigned           g_mm[2] = {0x7F800000u, 0u};        // min/max bits (idempotent)

// ---- 1) fused: min/max of weights + raw degree (sum,count packed u64 atomic) ---
__global__ void k_prepdeg(const int* __restrict__ ei, const float* __restrict__ ew) {
    unsigned lmin = 0x7F800000u, lmax = 0u;
    for (int e = blockIdx.x * blockDim.x + threadIdx.x; e < N_EDGES;
         e += gridDim.x * blockDim.x) {
        float w = ew[e];
        int   c = ei[N_EDGES + e];                     // dst = edge_index[1][e]
        unsigned b = __float_as_uint(w);               // nonneg: uint order == float order
        lmin = min(lmin, b);
        lmax = max(lmax, b);
        // pack: count in bits[52,64), raw-weight sum as 32-bit fixed point below
        unsigned long long pk = (1ULL << 52) |
                                (unsigned long long)(w * 4294967296.0f);
        atomicAdd(&g_pack[c], pk);
    }
    lmin = __reduce_min_sync(0xffffffffu, lmin);
    lmax = __reduce_max_sync(0xffffffffu, lmax);
    __shared__ unsigned smin[8], smax[8];
    int wid = threadIdx.x >> 5, lane = threadIdx.x & 31;
    if (lane == 0) { smin[wid] = lmin; smax[wid] = lmax; }
    __syncthreads();
    if (threadIdx.x == 0) {
        unsigned bmin = smin[0], bmax = smax[0];
        for (int w = 1; w < 8; w++) { bmin = min(bmin, smin[w]); bmax = max(bmax, smax[w]); }
        atomicMin(&g_mm[0], bmin);
        atomicMax(&g_mm[1], bmax);
    }
}

// ---- 2) dinv = rsqrt(deg), A = dinv^2 * x (one pass); resets g_pack ------------
__global__ void k_rsqrtself(const float* __restrict__ x) {
    int idx = blockIdx.x * blockDim.x + threadIdx.x;   // over 800000 float4s
    if (idx >= N_NODES * (D_IN / 4)) return;
    int row = idx >> 4;                                // 16 float4 per row

    unsigned long long v = g_pack[row];                // warp-broadcast (same row/16 lanes)
    float cnt = (float)(unsigned)(v >> 52);
    float sum = (float)(v & ((1ULL << 52) - 1)) * (1.0f / 4294967296.0f);
    float mn  = __uint_as_float(g_mm[0]);
    float inv = 1.0f / (__uint_as_float(g_mm[1]) - mn);
    float deg = 1.0f + (sum - cnt * mn) * inv;         // 1 = self-loop
    float di  = rsqrtf(deg);
    float dd  = di * di;

    float4 xv = ((const float4*)x)[idx];
    xv.x *= dd; xv.y *= dd; xv.z *= dd; xv.w *= dd;
    g_A4[idx] = xv;
    if ((idx & 15) == 0) {                             // one writer per row (loads of all
        g_dinv[row] = di;                              //  16 lanes precede this store)
        g_pack[row] = 0ull;                            // clean state for next replay
    }
}

// ---- 3) edge scatter: A[col] += norm * x[row], red.global.add.v4.f32 -----------
__device__ __forceinline__ void red_add_v4(float* p, float4 v) {
    asm volatile("red.global.add.v4.f32 [%0], {%1,%2,%3,%4};"
                 :: "l"(p), "f"(v.x), "f"(v.y), "f"(v.z), "f"(v.w)
                 : "memory");
}

__global__ void __launch_bounds__(256) k_edges(const int* __restrict__ ei,
                                               const float* __restrict__ ew,
                                               const float* __restrict__ x) {
    int lane  = threadIdx.x & 31;
    int gwarp = (blockIdx.x * blockDim.x + threadIdx.x) >> 5;
    int e = gwarp * 32 + lane;           // N_EDGES = 25000*32: no tail

    float mn  = __uint_as_float(g_mm[0]);
    float inv = 1.0f / (__uint_as_float(g_mm[1]) - mn);

    int   r = ei[e];                     // src = edge_index[0][e]
    int   c = ei[N_EDGES + e];           // dst = edge_index[1][e]
    float w = (ew[e] - mn) * inv;
    float nrm = g_dinv[r] * w * g_dinv[c];

    int half = lane >> 4;                // 0: even edge, 1: odd edge
    int q    = lane & 15;                // float4 index within the 64-float row

#pragma unroll 4
    for (int i = 0; i < 32; i += 2) {
        int   rr = __shfl_sync(0xffffffffu, r,   i + half);
        int   cc = __shfl_sync(0xffffffffu, c,   i + half);
        float nn = __shfl_sync(0xffffffffu, nrm, i + half);
        float4 v = ((const float4*)x)[(size_t)rr * 16 + q];
        v.x *= nn; v.y *= nn; v.z *= nn; v.w *= nn;
        red_add_v4((float*)(g_A4 + (size_t)cc * 16 + q), v);
    }
}

// ---- 4) GEMM out = A @ W_cat + b via TF32 wmma (m16n16k8) ----------------------
// Block: 64 rows x 256 cols, 8 warps. Warp (rt = wid&3, ch = wid>>2):
//   rows [rt*16, rt*16+16), cols [ch*128, ch*128+128) = 8 wmma tiles.
// A staged in smem (guarded tail); W fragments loaded from global (64 KB total,
// L1/L2-resident across all blocks); bias pre-loaded into accumulators via a
// 16-row replicated smem tile.
__global__ void __launch_bounds__(256) k_gemm(const float* __restrict__ Ws,
                                              const float* __restrict__ bs,
                                              float* __restrict__ out) {
    __shared__ float as[64 * 64];       // 16 KB  A tile
    __shared__ float bias[16 * 256];    // 16 KB  bias replicated over 16 rows
    __shared__ float stage[8][256];     //  8 KB  per-warp staging (tail block only)

    const int tid  = threadIdx.x;
    const int wid  = tid >> 5;
    const int row0 = blockIdx.x * 64;
    const float* A = (const float*)g_A4;

    // stage A (64x64) with tail guard
#pragma unroll
    for (int s = 0; s < 16; s++) {
        int idx = tid + 256 * s;
        int r = idx >> 6;
        int gr = row0 + r;
        as[idx] = (gr < N_NODES) ? A[(size_t)gr * D_IN + (idx & 63)] : 0.0f;
    }
    // stage bias, replicated across 16 rows
#pragma unroll
    for (int s = 0; s < 16; s++) {
        int idx = tid + 256 * s;
        bias[idx] = bs[idx & 255];
    }
    __syncthreads();

    const int rt = wid & 3;             // row tile 0..3
    const int ch = wid >> 2;            // col half 0..1
    const int cbase = ch * 128;

    wmma::fragment<wmma::accumulator, 16, 16, 8, float> acc[8];
#pragma unroll
    for (int ct = 0; ct < 8; ct++)
        wmma::load_matrix_sync(acc[ct], &bias[cbase + ct * 16], 256, wmma::mem_row_major);

#pragma unroll
    for (int k0 = 0; k0 < 8; k0++) {    // K = 64 in steps of 8
        wmma::fragment<wmma::matrix_a, 16, 16, 8, wmma::precision::tf32,
                       wmma::row_major> a;
        wmma::load_matrix_sync(a, &as[rt * 16 * 64 + k0 * 8], 64);
#pragma unroll
        for (int t = 0; t < a.num_elements; t++) a.x[t] = wmma::__float_to_tf32(a.x[t]);

#pragma unroll
        for (int ct = 0; ct < 8; ct++) {
            int c = cbase + ct * 16;    // 16-col tile never crosses a 64-col scale
            // W_cat[k][c] = Ws[(c>>6)*4096 + k*64 + (c&63)], row stride 64
            const float* bp = Ws + (size_t)(c >> 6) * 4096 + (size_t)k0 * 8 * 64 + (c & 63);
            wmma::fragment<wmma::matrix_b, 16, 16, 8, wmma::precision::tf32,
                           wmma::row_major> b;
            wmma::load_matrix_sync(b, bp, 64);
#pragma unroll
            for (int t = 0; t < b.num_elements; t++)
                b.x[t] = wmma::__float_to_tf32(b.x[t]);
            wmma::mma_sync(acc[ct], a, b, acc[ct]);
        }
    }

    if (row0 + 64 <= N_NODES) {
        // full block: direct stores
#pragma unroll
        for (int ct = 0; ct < 8; ct++)
            wmma::store_matrix_sync(&out[(size_t)(row0 + rt * 16) * D_CAT + cbase + ct * 16],
                                    acc[ct], D_CAT, wmma::mem_row_major);
    } else {
        // tail block: stage per-warp 16x16, guarded scalar stores
        int lane = tid & 31;
        for (int ct = 0; ct < 8; ct++) {
            wmma::store_matrix_sync(stage[wid], acc[ct], 16, wmma::mem_row_major);
            __syncwarp();
#pragma unroll
            for (int s = 0; s < 8; s++) {
                int e = lane + 32 * s;          // 256 elems / 32 lanes
                int r = row0 + rt * 16 + (e >> 4);
                if (r < N_NODES)
                    out[(size_t)r * D_CAT + cbase + ct * 16 + (e & 15)] = stage[wid][e];
            }
            __syncwarp();
        }
    }
}

// ---------------- launch -------------------------------------------------------
extern "C" void kernel_launch(void* const* d_in, const int* in_sizes, int n_in,
                              void* d_out, int out_size) {
    // Resolve inputs by element count (all five distinct):
    //   x=3,200,000 f32 | edge_index=1,600,000 i32 | edge_weight=800,000 f32
    //   Ws=16,384 f32   | bs=256 f32
    const float* x  = nullptr;
    const int*   ei = nullptr;
    const float* ew = nullptr;
    const float* Ws = nullptr;
    const float* bs = nullptr;
    for (int i = 0; i < n_in; i++) {
        switch (in_sizes[i]) {
            case 3200000: x  = (const float*)d_in[i]; break;
            case 1600000: ei = (const int*)d_in[i];   break;
            case  800000: ew = (const float*)d_in[i]; break;
            case   16384: Ws = (const float*)d_in[i]; break;
            case     256: bs = (const float*)d_in[i]; break;
        }
    }
    float* out = (float*)d_out;  // [50000, 256]

    k_prepdeg<<<256, 256>>>(ei, ew);                            // minmax + packed degree
    k_rsqrtself<<<(N_NODES * 16 + 255) / 256, 256>>>(x);        // dinv + A=dinv^2*x + reset
    k_edges<<<(N_EDGES / 32) / 8, 256>>>(ei, ew, x);            // 3125 blocks, v4 REDs
    k_gemm<<<(N_NODES + 63) / 64, 256>>>(Ws, bs, out);          // TF32 wmma GEMM + bias
}